// round 6
// baseline (speedup 1.0000x reference)
#include <cuda_runtime.h>
#include <cstdlib>

// Problem dims (LNCCLoss_15539191677017): [B=2, C=1, D=160, H=192, W=160] fp32
#define W_   160
#define H_   192
#define D_   160
#define NB   2
#define HW_  (H_ * W_)                 // 30720
#define NTOT (NB * D_ * HW_)           // 9830400

// Tile config: 32 x 8 outputs, 256 threads, 2 blocks/SM
#define TX   32
#define TY   8
#define IXW  40       // inner (products/means) = out + 8
#define IYH  16
#define RYH  24       // raw rows touched per slice (inner + 8)
#define ZC   40       // z-chunk
#define CZ   4
#define GX   5        // 160/32
#define GY   24       // 192/8
#define NBLK (GX * GY * CZ * NB)       // 960

// Smem pitches (floats)
#define P_IN   41
#define P_OUT  33

// Smem layout (float offsets)
#define OFF_RXB   0                          // ring xy-boxed inputs: 2 x 10 x (16*41)
#define SZ_XB_SL  (IYH * P_IN)               // 656
#define OFF_RPXB  (OFF_RXB + 2*10*SZ_XB_SL)  // ring xy-boxed products: 3 x 10 x (8*33)
#define SZ_PX_SL  (TY * P_OUT)               // 264
#define OFF_TMP   (OFF_RPXB + 3*10*SZ_PX_SL) // x-boxed scratch (union of uses)
#define TMP_FS    (RYH * P_IN + 1)           // 985  (inputs: 2 fields)
#define TMP2_FS   (IYH * P_OUT + 1)          // 529  (products: 3 fields; 3*529 <= 2*985)
#define OFF_PROD  (OFF_TMP + 2*TMP_FS)
#define OFF_SZS   (OFF_PROD + 3*SZ_XB_SL)
#define SMEM_FL   (OFF_SZS + 2*SZ_XB_SL)     // 26290 floats
#define SMEM_BYTES (SMEM_FL * 4)             // 105160 B -> 2 blocks/SM

__device__ float g_block[NBLK];

__device__ __forceinline__ int iclampi(int v, int lo, int hi) {
    return v < lo ? lo : (v > hi ? hi : v);
}

__global__ void __launch_bounds__(256, 2)
lncc_fused_kernel(const float* __restrict__ yt, const float* __restrict__ yp)
{
    extern __shared__ float sm[];
    const int tid = threadIdx.x;
    const int x0 = blockIdx.x * TX;
    const int y0 = blockIdx.y * TY;
    const int cz = blockIdx.z & 3;
    const int b  = blockIdx.z >> 2;
    const int z0 = cz * ZC;

    const float* __restrict__ bT = yt + (long)b * D_ * HW_;
    const float* __restrict__ bP = yp + (long)b * D_ * HW_;

    const int pLo = max(z0 - 4, 0);
    const int pHi = min(z0 + ZC + 3, D_ - 1);
    int zx = max(pLo - 4, 0);          // next raw slice to xy-box into the ring
    int next_out = z0;
    float rSn = 0.f, rSt = 0.f, rSp = 0.f;
    float acc = 0.f;
    const int aOut = (tid >> 5) * P_OUT + (tid & 31);  // oy=tid/32 (0..7), ox=tid%32
    const float inv_win = 1.0f / 729.0f;
    const float eps = 1e-6f;

    // Precompute x-box worker constants (f, r, s) and clamped row pointer parts.
    for (int zp = pLo; zp <= pHi; ++zp) {
        const int need = min(zp + 4, D_ - 1);

        // ---- Stage 1: xy-box input slices into ring (x-box reads gmem directly) ----
        while (zx <= need) {
            // x-box: 24 rows x 2 fields x 5 segs of 8 -> 240 workers
            if (tid < 240) {
                int f = tid & 1, w = tid >> 1;
                int r = w / 5, s = w - r * 5;
                const float* __restrict__ src = f ? bP : bT;
                int gy = iclampi(y0 - 8 + r, 0, H_ - 1);
                const float* __restrict__ rowp = src + (long)zx * HW_ + (long)gy * W_;
                float v[16];
                #pragma unroll
                for (int k = 0; k < 16; ++k)
                    v[k] = rowp[iclampi(x0 - 8 + s * 8 + k, 0, W_ - 1)];
                int dst = OFF_TMP + f * TMP_FS + r * P_IN + s * 8;
                float S = v[0]+v[1]+v[2]+v[3]+v[4]+v[5]+v[6]+v[7]+v[8];
                float keep = 0.f;
                #pragma unroll
                for (int j = 0; j < 8; ++j) {
                    sm[dst + j] = S;
                    if (s == 0 && j == 4) keep = S;   // ix=4 -> gx=x0 (edge if x0==0)
                    if (s == 4 && j == 3) keep = S;   // ix=35 -> gx=x0+31 (edge if x0==W-TX)
                    if (j < 7) S += v[j + 9] - v[j];
                }
                if (x0 == 0 && s == 0) {
                    sm[dst+0] = keep; sm[dst+1] = keep; sm[dst+2] = keep; sm[dst+3] = keep;
                }
                if (x0 == W_ - TX && s == 4) {
                    sm[dst+4] = keep; sm[dst+5] = keep; sm[dst+6] = keep; sm[dst+7] = keep;
                }
            }
            __syncthreads();
            // y-box -> ring slot: 40 cols x 2 fields x 2 segs of 8 -> 160 workers
            {
                const int slot = zx % 10;
                if (tid < 160) {
                    int f = tid & 1, w = tid >> 1;
                    int c = w >> 1, s = w & 1;
                    int src = OFF_TMP + f * TMP_FS + (s * 8) * P_IN + c;
                    int dst = OFF_RXB + (f * 10 + slot) * SZ_XB_SL + (s * 8) * P_IN + c;
                    float S = 0.f, keep = 0.f;
                    #pragma unroll
                    for (int k = 0; k < 9; ++k) S += sm[src + k * P_IN];
                    #pragma unroll
                    for (int j = 0; j < 8; ++j) {
                        sm[dst + j * P_IN] = S;
                        if (s == 0 && j == 4) keep = S;   // iy=4 -> gy=y0 (edge if y0==0)
                        if (s == 1 && j == 3) keep = S;   // iy=11 -> gy=y0+7 (edge if y0==H-TY)
                        if (j < 7) S += sm[src + (j + 9) * P_IN] - sm[src + j * P_IN];
                    }
                    if (y0 == 0 && s == 0) {
                        #pragma unroll
                        for (int j = 0; j < 4; ++j) sm[dst + j * P_IN] = keep;
                    }
                    if (y0 == H_ - TY && s == 1) {
                        #pragma unroll
                        for (int j = 4; j < 8; ++j) sm[dst + j * P_IN] = keep;
                    }
                }
            }
            __syncthreads();
            ++zx;
        }

        // ---- Stage 2: mean z-window advance + centered products at slice zp ----
        {
            const long sb = (long)zp * HW_;
            if (zp == pLo) {
                int sl[9];
                #pragma unroll
                for (int k = 0; k < 9; ++k) sl[k] = iclampi(zp - 4 + k, 0, D_ - 1) % 10;
                for (int i = tid; i < IXW * IYH; i += 256) {
                    int y = i / IXW, x = i - y * IXW;
                    int a = y * P_IN + x;
                    int gx = iclampi(x0 - 4 + x, 0, W_ - 1);
                    int gy = iclampi(y0 - 4 + y, 0, H_ - 1);
                    long o = sb + (long)gy * W_ + gx;
                    float t = bT[o], p = bP[o];
                    float st = 0.f, sp = 0.f;
                    #pragma unroll
                    for (int k = 0; k < 9; ++k) {
                        st += sm[OFF_RXB + sl[k] * SZ_XB_SL + a];
                        sp += sm[OFF_RXB + (10 + sl[k]) * SZ_XB_SL + a];
                    }
                    sm[OFF_SZS + a] = st;
                    sm[OFF_SZS + SZ_XB_SL + a] = sp;
                    float tc = t - st * inv_win, pc = p - sp * inv_win;
                    sm[OFF_PROD + a]                = tc * pc;
                    sm[OFF_PROD + SZ_XB_SL + a]     = tc * tc;
                    sm[OFF_PROD + 2 * SZ_XB_SL + a] = pc * pc;
                }
            } else {
                const int sN = (min(zp + 4, D_ - 1)) % 10;
                const int sO = (max(zp - 5, 0)) % 10;
                for (int i = tid; i < IXW * IYH; i += 256) {
                    int y = i / IXW, x = i - y * IXW;
                    int a = y * P_IN + x;
                    int gx = iclampi(x0 - 4 + x, 0, W_ - 1);
                    int gy = iclampi(y0 - 4 + y, 0, H_ - 1);
                    long o = sb + (long)gy * W_ + gx;
                    float t = bT[o], p = bP[o];
                    float st = sm[OFF_SZS + a]
                             + sm[OFF_RXB + sN * SZ_XB_SL + a]
                             - sm[OFF_RXB + sO * SZ_XB_SL + a];
                    float sp = sm[OFF_SZS + SZ_XB_SL + a]
                             + sm[OFF_RXB + (10 + sN) * SZ_XB_SL + a]
                             - sm[OFF_RXB + (10 + sO) * SZ_XB_SL + a];
                    sm[OFF_SZS + a] = st;
                    sm[OFF_SZS + SZ_XB_SL + a] = sp;
                    float tc = t - st * inv_win, pc = p - sp * inv_win;
                    sm[OFF_PROD + a]                = tc * pc;
                    sm[OFF_PROD + SZ_XB_SL + a]     = tc * tc;
                    sm[OFF_PROD + 2 * SZ_XB_SL + a] = pc * pc;
                }
            }
        }
        __syncthreads();

        // ---- Stage 3a: x-box products: 16 rows x 3 fields x 4 segs of 8 -> 192 workers ----
        if (tid < 192) {
            int f = tid % 3, w = tid / 3;
            int r = w >> 2, s = w & 3;
            int src = OFF_PROD + f * SZ_XB_SL + r * P_IN + s * 8;
            int dst = OFF_TMP + f * TMP2_FS + r * P_OUT + s * 8;
            float S = 0.f;
            #pragma unroll
            for (int k = 0; k < 9; ++k) S += sm[src + k];
            #pragma unroll
            for (int j = 0; j < 8; ++j) {
                sm[dst + j] = S;
                if (j < 7) S += sm[src + j + 9] - sm[src + j];
            }
        }
        __syncthreads();
        // ---- Stage 3b: y-box products -> ring slot: 32 cols x 3 fields -> 96 workers ----
        {
            const int slot = zp % 10;
            if (tid < 96) {
                int f = tid % 3, c = tid / 3;   // c 0..31, 8 outputs each
                int src = OFF_TMP + f * TMP2_FS + c;
                int dst = OFF_RPXB + (f * 10 + slot) * SZ_PX_SL + c;
                float S = 0.f;
                #pragma unroll
                for (int k = 0; k < 9; ++k) S += sm[src + k * P_OUT];
                #pragma unroll
                for (int j = 0; j < 8; ++j) {
                    sm[dst + j * P_OUT] = S;
                    if (j < 7) S += sm[src + (j + 9) * P_OUT] - sm[src + j * P_OUT];
                }
            }
        }
        __syncthreads();

        // ---- Emit ready output slices (thread owns output elem aOut) ----
        while (next_out < z0 + ZC && min(next_out + 4, D_ - 1) <= zp) {
            if (next_out == z0) {
                rSn = rSt = rSp = 0.f;
                #pragma unroll
                for (int k = 0; k < 9; ++k) {
                    int s = iclampi(next_out - 4 + k, 0, D_ - 1) % 10;
                    rSn += sm[OFF_RPXB + s * SZ_PX_SL + aOut];
                    rSt += sm[OFF_RPXB + (10 + s) * SZ_PX_SL + aOut];
                    rSp += sm[OFF_RPXB + (20 + s) * SZ_PX_SL + aOut];
                }
            } else {
                int sN = (min(next_out + 4, D_ - 1)) % 10;
                int sO = (max(next_out - 5, 0)) % 10;
                rSn += sm[OFF_RPXB + sN * SZ_PX_SL + aOut] - sm[OFF_RPXB + sO * SZ_PX_SL + aOut];
                rSt += sm[OFF_RPXB + (10 + sN) * SZ_PX_SL + aOut] - sm[OFF_RPXB + (10 + sO) * SZ_PX_SL + aOut];
                rSp += sm[OFF_RPXB + (20 + sN) * SZ_PX_SL + aOut] - sm[OFF_RPXB + (20 + sO) * SZ_PX_SL + aOut];
            }
            float cc = (rSn * rSn + eps) / (rSt * rSp + eps);
            acc += fminf(fmaxf(cc, 0.f), 1.f);
            ++next_out;
        }
    }

    // ---- Block reduction (deterministic fixed tree) ----
    __syncthreads();
    float v = acc;
    #pragma unroll
    for (int o = 16; o; o >>= 1) v += __shfl_down_sync(0xffffffffu, v, o);
    if ((tid & 31) == 0) sm[tid >> 5] = v;
    __syncthreads();
    if (tid < 8) {
        float t = sm[tid];
        #pragma unroll
        for (int o = 4; o; o >>= 1) t += __shfl_down_sync(0xffu, t, o);
        if (tid == 0) {
            int flat = blockIdx.x + GX * (blockIdx.y + GY * blockIdx.z);
            g_block[flat] = t;
        }
    }
}

// Finalize: sum block partials in double (deterministic) and write -mean.
__global__ void lncc_finalize_kernel(float* __restrict__ out)
{
    const int t = threadIdx.x; // 32 threads
    double s = 0.0;
    for (int i = t; i < NBLK; i += 32) s += (double)g_block[i];
    #pragma unroll
    for (int o = 16; o; o >>= 1) s += __shfl_down_sync(0xffffffffu, s, o);
    if (t == 0) out[0] = (float)(-s / (double)NTOT);
}

namespace {
struct KInit {
    KInit() {
        setenv("CUDA_MODULE_LOADING", "EAGER", 1);
        cudaFuncSetAttribute(lncc_fused_kernel,
                             cudaFuncAttributeMaxDynamicSharedMemorySize, SMEM_BYTES);
        cudaFuncAttributes a;
        cudaFuncGetAttributes(&a, lncc_fused_kernel);
        cudaFuncGetAttributes(&a, lncc_finalize_kernel);
    }
};
KInit kinit_;
}

extern "C" void kernel_launch(void* const* d_in, const int* in_sizes, int n_in,
                              void* d_out, int out_size)
{
    const float* y_true = (const float*)d_in[0];
    const float* y_pred = (const float*)d_in[1];
    float* out = (float*)d_out;
    (void)in_sizes; (void)n_in; (void)out_size;

    cudaFuncSetAttribute(lncc_fused_kernel,
                         cudaFuncAttributeMaxDynamicSharedMemorySize, SMEM_BYTES);
    dim3 grid(GX, GY, CZ * NB);
    lncc_fused_kernel<<<grid, 256, SMEM_BYTES>>>(y_true, y_pred);
    lncc_finalize_kernel<<<1, 32>>>(out);
}

// round 7
// speedup vs baseline: 1.8728x; 1.8728x over previous
#include <cuda_runtime.h>
#include <cstdlib>

// Problem dims: [B=2, C=1, D=160, H=192, W=160] fp32
#define W_   160
#define H_   192
#define D_   160
#define NB   2
#define HW_  (H_ * W_)
#define NTOT (NB * D_ * HW_)

// Tile: 32 x 16 outputs, 512 threads, z-chunk 40
#define TX   32
#define TY   16
#define IXW  40      // inner width  (out + 8)
#define IYH  24      // inner height (out + 8)
#define RYH  32      // raw x-boxed rows (inner + 8)
#define ZC   40
#define CZ   4
#define GX   5
#define GY   12
#define NBLK (GX * GY * CZ * NB)   // 480

#define P_IN  41
#define P_OUT 33

// Smem layout (float offsets)
#define OFF_RXB   0                            // xy-boxed inputs ring: 2 x 10 x (24*41)
#define SZ_XB_SL  (IYH * P_IN)                 // 984
#define OFF_RPXB  (OFF_RXB + 2*10*SZ_XB_SL)    // xy-boxed products ring: 3 x 10 x (16*33)
#define SZ_PX_SL  (TY * P_OUT)                 // 528
#define OFF_TMP   (OFF_RPXB + 3*10*SZ_PX_SL)   // x-boxed scratch (union)
#define TMP_FS    (RYH * P_IN + 1)             // 1313 (inputs, 2 fields)
#define TMP2_FS   (IYH * P_OUT + 1)            // 793  (products, 3 fields; 3*793 < 2*1313)
#define OFF_PROD  (OFF_TMP + 2*TMP_FS)
#define SMEM_FL   (OFF_PROD + 3*SZ_XB_SL)      // 41098 floats
#define SMEM_BYTES (SMEM_FL * 4)               // 164392 B

__device__ float g_block[NBLK];
__device__ int   g_count;   // zero-initialized; reset by last block each run

__device__ __forceinline__ int iclampi(int v, int lo, int hi) {
    return v < lo ? lo : (v > hi ? hi : v);
}

__global__ void __launch_bounds__(512, 1)
lncc_fused_kernel(const float* __restrict__ yt, const float* __restrict__ yp,
                  float* __restrict__ out)
{
    extern __shared__ float sm[];
    __shared__ int s_last;
    __shared__ double wsd[16];

    const int tid = threadIdx.x;
    const int x0 = blockIdx.x * TX;
    const int y0 = blockIdx.y * TY;
    const int cz = blockIdx.z & 3;
    const int b  = blockIdx.z >> 2;
    const int z0 = cz * ZC;

    const float* __restrict__ bT = yt + (long)b * D_ * HW_;
    const float* __restrict__ bP = yp + (long)b * D_ * HW_;

    const int pLo = max(z0 - 4, 0);
    const int pHi = min(z0 + ZC + 3, D_ - 1);
    int zx = max(pLo - 4, 0);
    int next_out = z0;
    float rSn = 0.f, rSt = 0.f, rSp = 0.f;
    float acc = 0.f;
    const int aOut = (tid >> 5) * P_OUT + (tid & 31);
    const float inv_win = 1.0f / 729.0f;
    const float eps = 1e-6f;

    // Stage-1 x-box worker constants: 512 workers = 2 fields x 32 rows x 8 segs(5 out)
    const int s1_f = tid >> 8;              // field
    const int s1_r = (tid & 255) >> 3;      // raw row 0..31
    const int s1_s = tid & 7;               // segment 0..7
    const int s1_gy = iclampi(y0 - 8 + s1_r, 0, H_ - 1);
    const float* __restrict__ s1_base = (s1_f ? bP : bT) + (long)s1_gy * W_;
    int s1_gx[13];
    #pragma unroll
    for (int k = 0; k < 13; ++k)
        s1_gx[k] = iclampi(x0 + s1_s * 5 - 8 + k, 0, W_ - 1);
    const int s1_dst = OFF_TMP + s1_f * TMP_FS + s1_r * P_IN + s1_s * 5;

    // Stage-2 fixed elem mapping (register z-window state)
    int   e_n = (tid < IXW * IYH - 512) ? 2 : 1;   // 448 threads get 2 elems
    long  e_go[2]; int e_a[2];
    {
        #pragma unroll
        for (int q = 0; q < 2; ++q) {
            int e = tid + q * 512;
            if (e >= IXW * IYH) e = IXW * IYH - 1;  // dummy (unused when e_n==1)
            int y = e / IXW, x = e - y * IXW;
            e_a[q]  = y * P_IN + x;
            int gx = iclampi(x0 - 4 + x, 0, W_ - 1);
            int gy = iclampi(y0 - 4 + y, 0, H_ - 1);
            e_go[q] = (long)gy * W_ + gx;
        }
    }
    float zst[2] = {0.f, 0.f}, zsp[2] = {0.f, 0.f};

    for (int zp = pLo; zp <= pHi; ++zp) {
        const int need = min(zp + 4, D_ - 1);

        // ---- Stage 1: xy-box input slice(s) into ring ----
        while (zx <= need) {
            // x-box straight from gmem: registers-sliding, all 512 threads
            {
                const float* __restrict__ rowp = s1_base + (long)zx * HW_;
                float v[13];
                #pragma unroll
                for (int k = 0; k < 13; ++k) v[k] = rowp[s1_gx[k]];
                float o[5];
                float S = v[0]+v[1]+v[2]+v[3]+v[4]+v[5]+v[6]+v[7]+v[8];
                o[0] = S;
                #pragma unroll
                for (int j = 1; j < 5; ++j) { S += v[j + 8] - v[j - 1]; o[j] = S; }
                if (x0 == 0 && s1_s == 0)       { o[0]=o[4]; o[1]=o[4]; o[2]=o[4]; o[3]=o[4]; }
                if (x0 == W_ - TX && s1_s == 7) { o[1]=o[0]; o[2]=o[0]; o[3]=o[0]; o[4]=o[0]; }
                #pragma unroll
                for (int j = 0; j < 5; ++j) sm[s1_dst + j] = o[j];
            }
            __syncthreads();
            // y-box -> ring slot: 240 workers = 2 fields x 3 segs(8 out) x 40 cols
            {
                const int slot = zx % 10;
                if (tid < 240) {
                    int c = tid % 40, q = tid / 40;
                    int sg = q % 3, f = q / 3;
                    int src = OFF_TMP + f * TMP_FS + (sg * 8) * P_IN + c;
                    float t[16];
                    #pragma unroll
                    for (int k = 0; k < 16; ++k) t[k] = sm[src + k * P_IN];
                    float o[8];
                    float S = t[0]+t[1]+t[2]+t[3]+t[4]+t[5]+t[6]+t[7]+t[8];
                    o[0] = S;
                    #pragma unroll
                    for (int j = 1; j < 8; ++j) { S += t[j + 8] - t[j - 1]; o[j] = S; }
                    if (y0 == 0 && sg == 0)       { o[0]=o[4]; o[1]=o[4]; o[2]=o[4]; o[3]=o[4]; }
                    if (y0 == H_ - TY && sg == 2) { o[4]=o[3]; o[5]=o[3]; o[6]=o[3]; o[7]=o[3]; }
                    int dst = OFF_RXB + (f * 10 + slot) * SZ_XB_SL + (sg * 8) * P_IN + c;
                    #pragma unroll
                    for (int j = 0; j < 8; ++j) sm[dst + j * P_IN] = o[j];
                }
            }
            __syncthreads();
            ++zx;
        }

        // ---- Stage 2: z-mean advance (register state) + centered products ----
        {
            const long sb = (long)zp * HW_;
            if (zp == pLo) {
                int sl[9];
                #pragma unroll
                for (int k = 0; k < 9; ++k) sl[k] = iclampi(zp - 4 + k, 0, D_ - 1) % 10;
                #pragma unroll
                for (int q = 0; q < 2; ++q) {
                    if (q < e_n) {
                        int a = e_a[q];
                        float st = 0.f, sp = 0.f;
                        #pragma unroll
                        for (int k = 0; k < 9; ++k) {
                            st += sm[OFF_RXB + sl[k] * SZ_XB_SL + a];
                            sp += sm[OFF_RXB + (10 + sl[k]) * SZ_XB_SL + a];
                        }
                        zst[q] = st; zsp[q] = sp;
                        float t = bT[sb + e_go[q]], p = bP[sb + e_go[q]];
                        float tc = t - st * inv_win, pc = p - sp * inv_win;
                        sm[OFF_PROD + a]                = tc * pc;
                        sm[OFF_PROD + SZ_XB_SL + a]     = tc * tc;
                        sm[OFF_PROD + 2 * SZ_XB_SL + a] = pc * pc;
                    }
                }
            } else {
                const int sN = (min(zp + 4, D_ - 1)) % 10;
                const int sO = (max(zp - 5, 0)) % 10;
                #pragma unroll
                for (int q = 0; q < 2; ++q) {
                    if (q < e_n) {
                        int a = e_a[q];
                        float st = zst[q] + sm[OFF_RXB + sN * SZ_XB_SL + a]
                                          - sm[OFF_RXB + sO * SZ_XB_SL + a];
                        float sp = zsp[q] + sm[OFF_RXB + (10 + sN) * SZ_XB_SL + a]
                                          - sm[OFF_RXB + (10 + sO) * SZ_XB_SL + a];
                        zst[q] = st; zsp[q] = sp;
                        float t = bT[sb + e_go[q]], p = bP[sb + e_go[q]];
                        float tc = t - st * inv_win, pc = p - sp * inv_win;
                        sm[OFF_PROD + a]                = tc * pc;
                        sm[OFF_PROD + SZ_XB_SL + a]     = tc * tc;
                        sm[OFF_PROD + 2 * SZ_XB_SL + a] = pc * pc;
                    }
                }
            }
        }
        __syncthreads();

        // ---- Stage 3a: x-box products: 288 workers = 3f x 24 rows x 4 segs(8 out) ----
        if (tid < 288) {
            int s = tid & 3, rest = tid >> 2;
            int r = rest % 24, f = rest / 24;
            int src = OFF_PROD + f * SZ_XB_SL + r * P_IN + s * 8;
            float t[16];
            #pragma unroll
            for (int k = 0; k < 16; ++k) t[k] = sm[src + k];
            int dst = OFF_TMP + f * TMP2_FS + r * P_OUT + s * 8;
            float S = t[0]+t[1]+t[2]+t[3]+t[4]+t[5]+t[6]+t[7]+t[8];
            sm[dst] = S;
            #pragma unroll
            for (int j = 1; j < 8; ++j) { S += t[j + 8] - t[j - 1]; sm[dst + j] = S; }
        }
        __syncthreads();
        // ---- Stage 3b: y-box products -> ring: 384 workers = 3f x 4 segs(4 out) x 32 cols ----
        {
            const int slot = zp % 10;
            if (tid < 384) {
                int c = tid % 32, rest = tid / 32;
                int sg = rest & 3, f = rest >> 2;
                int src = OFF_TMP + f * TMP2_FS + (sg * 4) * P_OUT + c;
                float t[12];
                #pragma unroll
                for (int k = 0; k < 12; ++k) t[k] = sm[src + k * P_OUT];
                int dst = OFF_RPXB + (f * 10 + slot) * SZ_PX_SL + (sg * 4) * P_OUT + c;
                float S = t[0]+t[1]+t[2]+t[3]+t[4]+t[5]+t[6]+t[7]+t[8];
                sm[dst] = S;
                #pragma unroll
                for (int j = 1; j < 4; ++j) {
                    S += t[j + 8] - t[j - 1];
                    sm[dst + j * P_OUT] = S;
                }
            }
        }
        __syncthreads();

        // ---- Emit ready output slices (thread owns one output elem) ----
        while (next_out < z0 + ZC && min(next_out + 4, D_ - 1) <= zp) {
            if (next_out == z0) {
                rSn = rSt = rSp = 0.f;
                #pragma unroll
                for (int k = 0; k < 9; ++k) {
                    int s = iclampi(next_out - 4 + k, 0, D_ - 1) % 10;
                    rSn += sm[OFF_RPXB + s * SZ_PX_SL + aOut];
                    rSt += sm[OFF_RPXB + (10 + s) * SZ_PX_SL + aOut];
                    rSp += sm[OFF_RPXB + (20 + s) * SZ_PX_SL + aOut];
                }
            } else {
                int sN = (min(next_out + 4, D_ - 1)) % 10;
                int sO = (max(next_out - 5, 0)) % 10;
                rSn += sm[OFF_RPXB + sN * SZ_PX_SL + aOut] - sm[OFF_RPXB + sO * SZ_PX_SL + aOut];
                rSt += sm[OFF_RPXB + (10 + sN) * SZ_PX_SL + aOut] - sm[OFF_RPXB + (10 + sO) * SZ_PX_SL + aOut];
                rSp += sm[OFF_RPXB + (20 + sN) * SZ_PX_SL + aOut] - sm[OFF_RPXB + (20 + sO) * SZ_PX_SL + aOut];
            }
            float cc = (rSn * rSn + eps) / (rSt * rSp + eps);
            acc += fminf(fmaxf(cc, 0.f), 1.f);
            ++next_out;
        }
    }

    // ---- Per-block reduction (deterministic fixed tree) ----
    __syncthreads();
    float v = acc;
    #pragma unroll
    for (int o = 16; o; o >>= 1) v += __shfl_down_sync(0xffffffffu, v, o);
    if ((tid & 31) == 0) sm[tid >> 5] = v;
    __syncthreads();
    const int flat = blockIdx.x + GX * (blockIdx.y + GY * blockIdx.z);
    if (tid < 16) {
        float t = sm[tid];
        #pragma unroll
        for (int o = 8; o; o >>= 1) t += __shfl_down_sync(0xffffu, t, o);
        if (tid == 0) g_block[flat] = t;
    }

    // ---- Last block finalizes (deterministic; saves a second launch) ----
    __threadfence();
    if (tid == 0) {
        int old = atomicAdd(&g_count, 1);
        s_last = (old == NBLK - 1);
    }
    __syncthreads();
    if (s_last) {
        double d = (tid < NBLK) ? (double)g_block[tid] : 0.0;
        #pragma unroll
        for (int o = 16; o; o >>= 1) d += __shfl_down_sync(0xffffffffu, d, o);
        if ((tid & 31) == 0) wsd[tid >> 5] = d;
        __syncthreads();
        if (tid < 16) {
            double t2 = wsd[tid];
            #pragma unroll
            for (int o = 8; o; o >>= 1) t2 += __shfl_down_sync(0xffffu, t2, o);
            if (tid == 0) {
                out[0] = (float)(-t2 / (double)NTOT);
                g_count = 0;   // reset for next graph replay
            }
        }
    }
}

namespace {
struct KInit {
    KInit() {
        setenv("CUDA_MODULE_LOADING", "EAGER", 1);
        cudaFuncSetAttribute(lncc_fused_kernel,
                             cudaFuncAttributeMaxDynamicSharedMemorySize, SMEM_BYTES);
        cudaFuncAttributes a;
        cudaFuncGetAttributes(&a, lncc_fused_kernel);
    }
};
KInit kinit_;
}

extern "C" void kernel_launch(void* const* d_in, const int* in_sizes, int n_in,
                              void* d_out, int out_size)
{
    const float* y_true = (const float*)d_in[0];
    const float* y_pred = (const float*)d_in[1];
    float* out = (float*)d_out;
    (void)in_sizes; (void)n_in; (void)out_size;

    cudaFuncSetAttribute(lncc_fused_kernel,
                         cudaFuncAttributeMaxDynamicSharedMemorySize, SMEM_BYTES);
    dim3 grid(GX, GY, CZ * NB);
    lncc_fused_kernel<<<grid, 512, SMEM_BYTES>>>(y_true, y_pred, out);
}